// round 1
// baseline (speedup 1.0000x reference)
#include <cuda_runtime.h>
#include <cuda_bf16.h>
#include <math.h>

// Problem constants (fixed by setup_inputs)
#define BATCH 2
#define SEQ   2048
#define DMODEL 2048
#define NHEADS 16
#define DHEAD 128
#define MROWS (BATCH*SEQ)          // 4096

// -------------------- scratch (static device globals; no allocation) ------
__device__ float g_q[MROWS * DMODEL];
__device__ float g_k[MROWS * DMODEL];
__device__ float g_v[MROWS * DMODEL];
__device__ float g_att[MROWS * DMODEL];

// ============================================================================
// SGEMM: C[M,N] = A[M,K] @ B[N,K]^T   (both row-major, K contiguous -> "NT")
// 128x128 tile, BK=16, 256 threads, 8x8 per-thread register tile.
// ============================================================================
__global__ __launch_bounds__(256)
void sgemm_nt(const float* __restrict__ A, const float* __restrict__ B,
              float* __restrict__ C, int M, int N, int K)
{
    __shared__ float As[16][132];   // As[k][m], stride 132 (16B aligned rows)
    __shared__ float Bs[16][132];   // Bs[k][n]

    const int tid = threadIdx.x;
    const int ty = tid >> 4;        // 0..15
    const int tx = tid & 15;        // 0..15
    const int m0 = blockIdx.y * 128;
    const int n0 = blockIdx.x * 128;

    const int lrow = tid >> 2;        // 0..63
    const int lc4  = (tid & 3) * 4;   // 0,4,8,12

    float acc[8][8];
#pragma unroll
    for (int i = 0; i < 8; i++)
#pragma unroll
        for (int j = 0; j < 8; j++) acc[i][j] = 0.f;

    for (int kb = 0; kb < K; kb += 16) {
#pragma unroll
        for (int ph = 0; ph < 2; ph++) {
            int r = lrow + ph * 64;
            float4 va = *(const float4*)&A[(size_t)(m0 + r) * K + kb + lc4];
            As[lc4+0][r] = va.x; As[lc4+1][r] = va.y;
            As[lc4+2][r] = va.z; As[lc4+3][r] = va.w;
            float4 vb = *(const float4*)&B[(size_t)(n0 + r) * K + kb + lc4];
            Bs[lc4+0][r] = vb.x; Bs[lc4+1][r] = vb.y;
            Bs[lc4+2][r] = vb.z; Bs[lc4+3][r] = vb.w;
        }
        __syncthreads();

#pragma unroll
        for (int k = 0; k < 16; k++) {
            float4 a0 = *(const float4*)&As[k][ty*8];
            float4 a1 = *(const float4*)&As[k][ty*8+4];
            float4 b0 = *(const float4*)&Bs[k][tx*8];
            float4 b1 = *(const float4*)&Bs[k][tx*8+4];
            float av[8] = {a0.x,a0.y,a0.z,a0.w,a1.x,a1.y,a1.z,a1.w};
            float bv[8] = {b0.x,b0.y,b0.z,b0.w,b1.x,b1.y,b1.z,b1.w};
#pragma unroll
            for (int i = 0; i < 8; i++)
#pragma unroll
                for (int j = 0; j < 8; j++)
                    acc[i][j] += av[i] * bv[j];
        }
        __syncthreads();
    }

#pragma unroll
    for (int i = 0; i < 8; i++) {
        float4 c0 = make_float4(acc[i][0], acc[i][1], acc[i][2], acc[i][3]);
        float4 c1 = make_float4(acc[i][4], acc[i][5], acc[i][6], acc[i][7]);
        size_t off = (size_t)(m0 + ty*8 + i) * N + n0 + tx*8;
        *(float4*)&C[off]     = c0;
        *(float4*)&C[off + 4] = c1;
    }
}

// ============================================================================
// RoPE (in-place on q and k). One thread per (b,s,h, d<64) pair.
// out[d]      = t[d]*cos[d]      - t[d+64]*sin[d]
// out[d+64]   = t[d+64]*cos[d+64] + t[d]*sin[d+64]
// ============================================================================
__global__ __launch_bounds__(256)
void rope_kernel(float* __restrict__ q, float* __restrict__ k,
                 const float* __restrict__ rc, const float* __restrict__ rs)
{
    int idx = blockIdx.x * 256 + threadIdx.x;
    const int total = BATCH * SEQ * NHEADS * 64;
    if (idx >= total) return;
    int d = idx & 63;
    int h = (idx >> 6) & (NHEADS - 1);
    int s = (idx >> 10) & (SEQ - 1);
    int b = idx >> 21;
    size_t base = ((size_t)(b * SEQ + s)) * DMODEL + h * DHEAD;
    float c0 = rc[s * DHEAD + d],      s0 = rs[s * DHEAD + d];
    float c1 = rc[s * DHEAD + 64 + d], s1 = rs[s * DHEAD + 64 + d];

    float q0 = q[base + d], q1 = q[base + 64 + d];
    q[base + d]      = q0 * c0 - q1 * s0;
    q[base + 64 + d] = q1 * c1 + q0 * s1;

    float k0 = k[base + d], k1 = k[base + 64 + d];
    k[base + d]      = k0 * c0 - k1 * s0;
    k[base + 64 + d] = k1 * c1 + k0 * s1;
}

// ============================================================================
// Flash attention: grid (S/64, H, B), 256 threads.
// Q tile 64x128 resident (prescaled by 1/sqrt(dh)); loop K/V tiles of 64.
// S-fragment: 16x16 threads * 4x4. O-fragment: 4 rows x 8 cols (128 cols/16 tx).
// ============================================================================
#define QS_STRIDE 68            // [128][68] transposed, float4-aligned rows
#define SS_STRIDE 68
#define ATT_SMEM_FLOATS (128*QS_STRIDE*2 + 64*128 + 64*SS_STRIDE + 3*64)
#define ATT_SMEM_BYTES  (ATT_SMEM_FLOATS * 4)

__global__ __launch_bounds__(256)
void attn_kernel(const float* __restrict__ q, const float* __restrict__ k,
                 const float* __restrict__ v, float* __restrict__ o)
{
    extern __shared__ float sm[];
    float* Qs   = sm;                       // [128][68]  (Qs[d][r])
    float* Ks   = Qs + 128 * QS_STRIDE;     // [128][68]  (Ks[d][r])
    float* Vs   = Ks + 128 * QS_STRIDE;     // [64][128]  row-major
    float* Ss   = Vs + 64 * 128;            // [64][68]
    float* mrow = Ss + 64 * SS_STRIDE;      // [64]
    float* lrow = mrow + 64;                // [64]
    float* arow = lrow + 64;                // [64]

    const int tid = threadIdx.x;
    const int ty = tid >> 4, tx = tid & 15;
    const int b = blockIdx.z, h = blockIdx.y;
    const int q0 = blockIdx.x * 64;
    const int row4 = ty * 4, col8 = tx * 8;
    const float scale = 0.088388347648318447f;   // 1/sqrt(128)

    const float* qp = q + ((size_t)(b * SEQ + q0)) * DMODEL + h * DHEAD;

    for (int i = tid; i < 64 * 128; i += 256) {
        int r = i >> 7, d = i & 127;
        Qs[d * QS_STRIDE + r] = qp[(size_t)r * DMODEL + d] * scale;
    }
    if (tid < 64) { mrow[tid] = -3.0e38f; lrow[tid] = 0.f; }

    float oacc[4][8];
#pragma unroll
    for (int i = 0; i < 4; i++)
#pragma unroll
        for (int j = 0; j < 8; j++) oacc[i][j] = 0.f;

    for (int kt = 0; kt < SEQ; kt += 64) {
        const float* kp = k + ((size_t)(b * SEQ + kt)) * DMODEL + h * DHEAD;
        const float* vp = v + ((size_t)(b * SEQ + kt)) * DMODEL + h * DHEAD;
        __syncthreads();   // previous PV done before overwriting Ks/Vs/Ss
        for (int i = tid; i < 64 * 128; i += 256) {
            int r = i >> 7, d = i & 127;
            Ks[d * QS_STRIDE + r] = kp[(size_t)r * DMODEL + d];
            Vs[r * 128 + d]       = vp[(size_t)r * DMODEL + d];
        }
        __syncthreads();

        // ---- S = (Q*scale) @ K^T, 4x4 per thread ----
        float sreg[4][4];
#pragma unroll
        for (int i = 0; i < 4; i++)
#pragma unroll
            for (int j = 0; j < 4; j++) sreg[i][j] = 0.f;

#pragma unroll 4
        for (int kk = 0; kk < 128; kk++) {
            float4 a  = *(const float4*)&Qs[kk * QS_STRIDE + row4];
            float4 bb = *(const float4*)&Ks[kk * QS_STRIDE + tx * 4];
            float av[4] = {a.x, a.y, a.z, a.w};
            float bv[4] = {bb.x, bb.y, bb.z, bb.w};
#pragma unroll
            for (int i = 0; i < 4; i++)
#pragma unroll
                for (int j = 0; j < 4; j++)
                    sreg[i][j] += av[i] * bv[j];
        }
#pragma unroll
        for (int i = 0; i < 4; i++)
#pragma unroll
            for (int j = 0; j < 4; j++)
                Ss[(row4 + i) * SS_STRIDE + tx * 4 + j] = sreg[i][j];
        __syncthreads();

        // ---- online softmax: 4 threads per row, 16 cols each ----
        {
            int row = tid >> 2, part = tid & 3;
            float* srow = Ss + row * SS_STRIDE + part * 16;
            float mloc = -3.0e38f;
#pragma unroll
            for (int c = 0; c < 16; c++) mloc = fmaxf(mloc, srow[c]);
            mloc = fmaxf(mloc, __shfl_xor_sync(0xffffffffu, mloc, 1));
            mloc = fmaxf(mloc, __shfl_xor_sync(0xffffffffu, mloc, 2));
            float mprev = mrow[row];
            float mnew  = fmaxf(mprev, mloc);
            float lsum = 0.f;
#pragma unroll
            for (int c = 0; c < 16; c++) {
                float p = __expf(srow[c] - mnew);
                srow[c] = p;
                lsum += p;
            }
            lsum += __shfl_xor_sync(0xffffffffu, lsum, 1);
            lsum += __shfl_xor_sync(0xffffffffu, lsum, 2);
            if (part == 0) {
                float alpha = __expf(mprev - mnew);   // 0 on first tile
                lrow[row] = lrow[row] * alpha + lsum;
                mrow[row] = mnew;
                arow[row] = alpha;
            }
        }
        __syncthreads();

        // ---- O = O*alpha + P @ V ----
        float al[4];
#pragma unroll
        for (int i = 0; i < 4; i++) al[i] = arow[row4 + i];
#pragma unroll
        for (int i = 0; i < 4; i++)
#pragma unroll
            for (int j = 0; j < 8; j++) oacc[i][j] *= al[i];

#pragma unroll 2
        for (int kk = 0; kk < 64; kk++) {
            float p0 = Ss[(row4 + 0) * SS_STRIDE + kk];
            float p1 = Ss[(row4 + 1) * SS_STRIDE + kk];
            float p2 = Ss[(row4 + 2) * SS_STRIDE + kk];
            float p3 = Ss[(row4 + 3) * SS_STRIDE + kk];
            float4 v0 = *(const float4*)&Vs[kk * 128 + col8];
            float4 v1 = *(const float4*)&Vs[kk * 128 + col8 + 4];
            float vv[8] = {v0.x, v0.y, v0.z, v0.w, v1.x, v1.y, v1.z, v1.w};
#pragma unroll
            for (int j = 0; j < 8; j++) {
                oacc[0][j] += p0 * vv[j];
                oacc[1][j] += p1 * vv[j];
                oacc[2][j] += p2 * vv[j];
                oacc[3][j] += p3 * vv[j];
            }
        }
    }

    // ---- epilogue: divide by l, write (b, s, h*128+d) layout ----
    float* op = o + ((size_t)(b * SEQ + q0)) * DMODEL + h * DHEAD;
#pragma unroll
    for (int i = 0; i < 4; i++) {
        float inv = 1.f / lrow[row4 + i];
        float4 c0 = make_float4(oacc[i][0]*inv, oacc[i][1]*inv, oacc[i][2]*inv, oacc[i][3]*inv);
        float4 c1 = make_float4(oacc[i][4]*inv, oacc[i][5]*inv, oacc[i][6]*inv, oacc[i][7]*inv);
        size_t off = (size_t)(row4 + i) * DMODEL + col8;
        *(float4*)&op[off]     = c0;
        *(float4*)&op[off + 4] = c1;
    }
}

// ============================================================================
extern "C" void kernel_launch(void* const* d_in, const int* in_sizes, int n_in,
                              void* d_out, int out_size)
{
    const float* x  = (const float*)d_in[0];
    const float* rc = (const float*)d_in[1];
    const float* rs = (const float*)d_in[2];
    const float* Wq = (const float*)d_in[3];
    const float* Wk = (const float*)d_in[4];
    const float* Wv = (const float*)d_in[5];
    const float* Wo = (const float*)d_in[6];
    float* out = (float*)d_out;

    float *q, *k, *v, *att;
    cudaGetSymbolAddress((void**)&q,   g_q);
    cudaGetSymbolAddress((void**)&k,   g_k);
    cudaGetSymbolAddress((void**)&v,   g_v);
    cudaGetSymbolAddress((void**)&att, g_att);

    cudaFuncSetAttribute(attn_kernel,
                         cudaFuncAttributeMaxDynamicSharedMemorySize,
                         ATT_SMEM_BYTES);

    dim3 gg(DMODEL / 128, MROWS / 128);   // (16, 32)
    dim3 bb(256);

    sgemm_nt<<<gg, bb>>>(x, Wq, q, MROWS, DMODEL, DMODEL);
    sgemm_nt<<<gg, bb>>>(x, Wk, k, MROWS, DMODEL, DMODEL);
    sgemm_nt<<<gg, bb>>>(x, Wv, v, MROWS, DMODEL, DMODEL);

    int rope_threads = BATCH * SEQ * NHEADS * 64;
    rope_kernel<<<(rope_threads + 255) / 256, 256>>>(q, k, rc, rs);

    attn_kernel<<<dim3(SEQ / 64, NHEADS, BATCH), 256, ATT_SMEM_BYTES>>>(q, k, v, att);

    sgemm_nt<<<gg, bb>>>(att, Wo, out, MROWS, DMODEL, DMODEL);
}

// round 3
// speedup vs baseline: 1.4382x; 1.4382x over previous
#include <cuda_runtime.h>
#include <cuda_bf16.h>
#include <math.h>
#include <stdint.h>

// Problem constants
#define BATCH 2
#define SEQ   2048
#define DMODEL 2048
#define NHEADS 16
#define DHEAD 128
#define MROWS (BATCH*SEQ)          // 4096
#define KDIM  DMODEL

// -------------------- scratch (static device globals; no allocation) ------
__device__ float g_q[MROWS * DMODEL];
__device__ float g_k[MROWS * DMODEL];
__device__ float g_v[MROWS * DMODEL];
__device__ float g_att[MROWS * DMODEL];

// bf16 hi/lo planes, plain row-major [rows][2048]
__device__ __align__(16) __nv_bfloat16 g_xhi[MROWS * DMODEL];
__device__ __align__(16) __nv_bfloat16 g_xlo[MROWS * DMODEL];
__device__ __align__(16) __nv_bfloat16 g_wqhi[DMODEL * DMODEL];
__device__ __align__(16) __nv_bfloat16 g_wqlo[DMODEL * DMODEL];
__device__ __align__(16) __nv_bfloat16 g_wkhi[DMODEL * DMODEL];
__device__ __align__(16) __nv_bfloat16 g_wklo[DMODEL * DMODEL];
__device__ __align__(16) __nv_bfloat16 g_wvhi[DMODEL * DMODEL];
__device__ __align__(16) __nv_bfloat16 g_wvlo[DMODEL * DMODEL];
__device__ __align__(16) __nv_bfloat16 g_wohi[DMODEL * DMODEL];
__device__ __align__(16) __nv_bfloat16 g_wolo[DMODEL * DMODEL];
__device__ __align__(16) __nv_bfloat16 g_atthi[MROWS * DMODEL];
__device__ __align__(16) __nv_bfloat16 g_attlo[MROWS * DMODEL];

// ============================ PTX helpers (sm_80-baseline only) ============
__device__ __forceinline__ uint32_t smem_u32(const void* p) {
    uint32_t a;
    asm("{ .reg .u64 t; cvta.to.shared.u64 t, %1; cvt.u32.u64 %0, t; }" : "=r"(a) : "l"(p));
    return a;
}
#define CP_ASYNC16(dst, src) \
    asm volatile("cp.async.cg.shared.global [%0], [%1], 16;" :: "r"(dst), "l"(src))
#define CP_COMMIT() asm volatile("cp.async.commit_group;" ::: "memory")
#define CP_WAIT(n)  asm volatile("cp.async.wait_group %0;" :: "n"(n) : "memory")

#define LDSM4(r0, r1, r2, r3, addr) \
    asm volatile("ldmatrix.sync.aligned.m8n8.x4.shared.b16 {%0,%1,%2,%3}, [%4];" \
        : "=r"(r0), "=r"(r1), "=r"(r2), "=r"(r3) : "r"(addr))

#define MMA16816(c, a, b) \
    asm volatile("mma.sync.aligned.m16n8k16.row.col.f32.bf16.bf16.f32 " \
        "{%0,%1,%2,%3},{%4,%5,%6,%7},{%8,%9},{%0,%1,%2,%3};" \
        : "+f"((c)[0]), "+f"((c)[1]), "+f"((c)[2]), "+f"((c)[3]) \
        : "r"((a)[0]), "r"((a)[1]), "r"((a)[2]), "r"((a)[3]), "r"((b)[0]), "r"((b)[1]))

// ============================================================================
// pack_split: fp32 row-major -> bf16 hi/lo planes (plain row-major).
// One thread per 2 elements (one uint32 per plane).
// ============================================================================
__global__ __launch_bounds__(256)
void pack_split(const float* __restrict__ src,
                uint32_t* __restrict__ hi, uint32_t* __restrict__ lo, int npairs)
{
    int i = blockIdx.x * 256 + threadIdx.x;
    if (i >= npairs) return;
    float2 v = ((const float2*)src)[i];
    __nv_bfloat16 h0 = __float2bfloat16(v.x);
    __nv_bfloat16 h1 = __float2bfloat16(v.y);
    __nv_bfloat16 l0 = __float2bfloat16(v.x - __bfloat162float(h0));
    __nv_bfloat16 l1 = __float2bfloat16(v.y - __bfloat162float(h1));
    hi[i] = (uint32_t)__bfloat16_as_ushort(h0) | ((uint32_t)__bfloat16_as_ushort(h1) << 16);
    lo[i] = (uint32_t)__bfloat16_as_ushort(l0) | ((uint32_t)__bfloat16_as_ushort(l1) << 16);
}

// ============================================================================
// gemm_mma: C[M,2048] = A @ B^T via mma.sync bf16 hi/lo split (3 products).
// CTA 128x128, BK=32, 8 warps (2m x 4n), warp tile 64x32, 3-stage cp.async.
// Smem tiles [128][32] bf16, 64B rows, chunk swizzle: pch = ch ^ ((row>>1)&3).
// ============================================================================
#define BKD 32
#define TILE_B   (128 * BKD * 2)              // 8192 bytes per plane tile
#define STAGE_B  (4 * TILE_B)                 // Ahi, Alo, Bhi, Blo = 32 KB
#define GSTAGES  3
#define GEMM_SMEM (GSTAGES * STAGE_B)         // 96 KB

__global__ __launch_bounds__(256)
void gemm_mma(const __nv_bfloat16* __restrict__ Ahi, const __nv_bfloat16* __restrict__ Alo,
              const __nv_bfloat16* __restrict__ Bhi, const __nv_bfloat16* __restrict__ Blo,
              float* __restrict__ C)
{
    extern __shared__ char smc[];
    const uint32_t sb = smem_u32(smc);

    const int tid  = threadIdx.x;
    const int lane = tid & 31;
    const int wid  = tid >> 5;
    const int wm   = wid & 1;          // 0..1  (64 rows each)
    const int wn   = wid >> 1;         // 0..3  (32 cols each)
    const int m0   = blockIdx.y * 128;
    const int n0   = blockIdx.x * 128;

    // per-thread load slots: idx in [0,512): row=idx>>2, chunk=idx&3
    const int r1 = tid >> 2, c1 = tid & 3;
    const int r2 = (tid + 256) >> 2, c2 = (tid + 256) & 3;
    const uint32_t d1 = (uint32_t)(r1 * 64 + ((c1 ^ ((r1 >> 1) & 3)) * 16));
    const uint32_t d2 = (uint32_t)(r2 * 64 + ((c2 ^ ((r2 >> 1) & 3)) * 16));

    const __nv_bfloat16* srcA[2] = { Ahi + (size_t)m0 * KDIM, Alo + (size_t)m0 * KDIM };
    const __nv_bfloat16* srcB[2] = { Bhi + (size_t)n0 * KDIM, Blo + (size_t)n0 * KDIM };

    auto load_stage = [&](int s, int kb) {
        uint32_t base = sb + s * STAGE_B;
        int koff = kb * BKD;
#pragma unroll
        for (int t = 0; t < 2; t++) {
            CP_ASYNC16(base + t * TILE_B + d1, srcA[t] + (size_t)r1 * KDIM + koff + c1 * 8);
            CP_ASYNC16(base + t * TILE_B + d2, srcA[t] + (size_t)r2 * KDIM + koff + c2 * 8);
            CP_ASYNC16(base + (2 + t) * TILE_B + d1, srcB[t] + (size_t)r1 * KDIM + koff + c1 * 8);
            CP_ASYNC16(base + (2 + t) * TILE_B + d2, srcB[t] + (size_t)r2 * KDIM + koff + c2 * 8);
        }
    };

    float acc[4][4][4];
#pragma unroll
    for (int i = 0; i < 4; i++)
#pragma unroll
        for (int j = 0; j < 4; j++)
#pragma unroll
            for (int r = 0; r < 4; r++) acc[i][j][r] = 0.f;

    load_stage(0, 0); CP_COMMIT();
    load_stage(1, 1); CP_COMMIT();

    // ldmatrix lane addressing (constant across stages, modulo stage base)
    const int arow = wm * 64 + (lane & 15);            // A: rows (per m-frag +16*i)
    const int bnrow = wn * 32 + (lane & 7) + ((lane >> 3) & 1) * 8;  // B (per jp +16)
    const int lhalf = lane >> 4;                       // 16B half select

    const int NKB = KDIM / BKD;                        // 64
    for (int kc = 0; kc < NKB; kc++) {
        CP_WAIT(1);
        __syncthreads();
        if (kc + 2 < NKB) load_stage((kc + 2) % GSTAGES, kc + 2);
        CP_COMMIT();

        uint32_t base = sb + (kc % GSTAGES) * STAGE_B;
        uint32_t aHb = base, aLb = base + TILE_B, bHb = base + 2 * TILE_B, bLb = base + 3 * TILE_B;

#pragma unroll
        for (int ks = 0; ks < 2; ks++) {
            uint32_t ah[4][4], al[4][4], bh[4][2], bl[4][2];
#pragma unroll
            for (int i = 0; i < 4; i++) {
                int row = arow + i * 16;
                uint32_t off = (uint32_t)(row * 64 + (((ks * 2 + lhalf) ^ ((row >> 1) & 3)) * 16));
                LDSM4(ah[i][0], ah[i][1], ah[i][2], ah[i][3], aHb + off);
                LDSM4(al[i][0], al[i][1], al[i][2], al[i][3], aLb + off);
            }
#pragma unroll
            for (int jp = 0; jp < 2; jp++) {
                int row = bnrow + jp * 16;
                uint32_t off = (uint32_t)(row * 64 + (((ks * 2 + lhalf) ^ ((row >> 1) & 3)) * 16));
                uint32_t r0, r1_, r2_, r3_;
                LDSM4(r0, r1_, r2_, r3_, bHb + off);
                bh[2 * jp][0] = r0;  bh[2 * jp][1] = r2_;
                bh[2 * jp + 1][0] = r1_; bh[2 * jp + 1][1] = r3_;
                LDSM4(r0, r1_, r2_, r3_, bLb + off);
                bl[2 * jp][0] = r0;  bl[2 * jp][1] = r2_;
                bl[2 * jp + 1][0] = r1_; bl[2 * jp + 1][1] = r3_;
            }
#pragma unroll
            for (int i = 0; i < 4; i++)
#pragma unroll
                for (int j = 0; j < 4; j++) {
                    MMA16816(acc[i][j], ah[i], bh[j]);
                    MMA16816(acc[i][j], ah[i], bl[j]);
                    MMA16816(acc[i][j], al[i], bh[j]);
                }
        }
    }

    // epilogue
#pragma unroll
    for (int i = 0; i < 4; i++) {
#pragma unroll
        for (int j = 0; j < 4; j++) {
            int m = m0 + wm * 64 + i * 16 + (lane >> 2);
            int n = n0 + wn * 32 + j * 8 + (lane & 3) * 2;
            *(float2*)&C[(size_t)m * DMODEL + n]       = make_float2(acc[i][j][0], acc[i][j][1]);
            *(float2*)&C[(size_t)(m + 8) * DMODEL + n] = make_float2(acc[i][j][2], acc[i][j][3]);
        }
    }
}

// ============================================================================
// RoPE (in-place on q and k)
// ============================================================================
__global__ __launch_bounds__(256)
void rope_kernel(float* __restrict__ q, float* __restrict__ k,
                 const float* __restrict__ rc, const float* __restrict__ rs)
{
    int idx = blockIdx.x * 256 + threadIdx.x;
    const int total = BATCH * SEQ * NHEADS * 64;
    if (idx >= total) return;
    int d = idx & 63;
    int h = (idx >> 6) & (NHEADS - 1);
    int s = (idx >> 10) & (SEQ - 1);
    int b = idx >> 21;
    size_t base = ((size_t)(b * SEQ + s)) * DMODEL + h * DHEAD;
    float c0 = rc[s * DHEAD + d],      s0 = rs[s * DHEAD + d];
    float c1 = rc[s * DHEAD + 64 + d], s1 = rs[s * DHEAD + 64 + d];

    float q0 = q[base + d], q1 = q[base + 64 + d];
    q[base + d]      = q0 * c0 - q1 * s0;
    q[base + 64 + d] = q1 * c1 + q0 * s1;

    float k0 = k[base + d], k1 = k[base + 64 + d];
    k[base + d]      = k0 * c0 - k1 * s0;
    k[base + 64 + d] = k1 * c1 + k0 * s1;
}

// ============================================================================
// Flash attention (fp32, unchanged from R1)
// ============================================================================
#define QS_STRIDE 68
#define SS_STRIDE 68
#define ATT_SMEM_FLOATS (128*QS_STRIDE*2 + 64*128 + 64*SS_STRIDE + 3*64)
#define ATT_SMEM_BYTES  (ATT_SMEM_FLOATS * 4)

__global__ __launch_bounds__(256)
void attn_kernel(const float* __restrict__ q, const float* __restrict__ k,
                 const float* __restrict__ v, float* __restrict__ o)
{
    extern __shared__ float smf[];
    float* Qs   = smf;
    float* Ks   = Qs + 128 * QS_STRIDE;
    float* Vs   = Ks + 128 * QS_STRIDE;
    float* Ss   = Vs + 64 * 128;
    float* mrow = Ss + 64 * SS_STRIDE;
    float* lrow = mrow + 64;
    float* arow = lrow + 64;

    const int tid = threadIdx.x;
    const int ty = tid >> 4, tx = tid & 15;
    const int b = blockIdx.z, h = blockIdx.y;
    const int q0 = blockIdx.x * 64;
    const int row4 = ty * 4, col8 = tx * 8;
    const float scale = 0.088388347648318447f;

    const float* qp = q + ((size_t)(b * SEQ + q0)) * DMODEL + h * DHEAD;

    for (int i = tid; i < 64 * 128; i += 256) {
        int r = i >> 7, d = i & 127;
        Qs[d * QS_STRIDE + r] = qp[(size_t)r * DMODEL + d] * scale;
    }
    if (tid < 64) { mrow[tid] = -3.0e38f; lrow[tid] = 0.f; }

    float oacc[4][8];
#pragma unroll
    for (int i = 0; i < 4; i++)
#pragma unroll
        for (int j = 0; j < 8; j++) oacc[i][j] = 0.f;

    for (int kt = 0; kt < SEQ; kt += 64) {
        const float* kp = k + ((size_t)(b * SEQ + kt)) * DMODEL + h * DHEAD;
        const float* vp = v + ((size_t)(b * SEQ + kt)) * DMODEL + h * DHEAD;
        __syncthreads();
        for (int i = tid; i < 64 * 128; i += 256) {
            int r = i >> 7, d = i & 127;
            Ks[d * QS_STRIDE + r] = kp[(size_t)r * DMODEL + d];
            Vs[r * 128 + d]       = vp[(size_t)r * DMODEL + d];
        }
        __syncthreads();

        float sreg[4][4];
#pragma unroll
        for (int i = 0; i < 4; i++)
#pragma unroll
            for (int j = 0; j < 4; j++) sreg[i][j] = 0.f;

#pragma unroll 4
        for (int kk = 0; kk < 128; kk++) {
            float4 a  = *(const float4*)&Qs[kk * QS_STRIDE + row4];
            float4 bb = *(const float4*)&Ks[kk * QS_STRIDE + tx * 4];
            float av[4] = {a.x, a.y, a.z, a.w};
            float bv[4] = {bb.x, bb.y, bb.z, bb.w};
#pragma unroll
            for (int i = 0; i < 4; i++)
#pragma unroll
                for (int j = 0; j < 4; j++)
                    sreg[i][j] += av[i] * bv[j];
        }
#pragma unroll
        for (int i = 0; i < 4; i++)
#pragma unroll
            for (int j = 0; j < 4; j++)
                Ss[(row4 + i) * SS_STRIDE + tx * 4 + j] = sreg[i][j];
        __syncthreads();

        {
            int row = tid >> 2, part = tid & 3;
            float* srow = Ss + row * SS_STRIDE + part * 16;
            float mloc = -3.0e38f;
#pragma unroll
            for (int c = 0; c < 16; c++) mloc = fmaxf(mloc, srow[c]);
            mloc = fmaxf(mloc, __shfl_xor_sync(0xffffffffu, mloc, 1));
            mloc = fmaxf(mloc, __shfl_xor_sync(0xffffffffu, mloc, 2));
            float mprev = mrow[row];
            float mnew  = fmaxf(mprev, mloc);
            float lsum = 0.f;
#pragma unroll
            for (int c = 0; c < 16; c++) {
                float p = __expf(srow[c] - mnew);
                srow[c] = p;
                lsum += p;
            }
            lsum += __shfl_xor_sync(0xffffffffu, lsum, 1);
            lsum += __shfl_xor_sync(0xffffffffu, lsum, 2);
            if (part == 0) {
                float alpha = __expf(mprev - mnew);
                lrow[row] = lrow[row] * alpha + lsum;
                mrow[row] = mnew;
                arow[row] = alpha;
            }
        }
        __syncthreads();

        float al[4];
#pragma unroll
        for (int i = 0; i < 4; i++) al[i] = arow[row4 + i];
#pragma unroll
        for (int i = 0; i < 4; i++)
#pragma unroll
            for (int j = 0; j < 8; j++) oacc[i][j] *= al[i];

#pragma unroll 2
        for (int kk = 0; kk < 64; kk++) {
            float p0 = Ss[(row4 + 0) * SS_STRIDE + kk];
            float p1 = Ss[(row4 + 1) * SS_STRIDE + kk];
            float p2 = Ss[(row4 + 2) * SS_STRIDE + kk];
            float p3 = Ss[(row4 + 3) * SS_STRIDE + kk];
            float4 v0 = *(const float4*)&Vs[kk * 128 + col8];
            float4 v1 = *(const float4*)&Vs[kk * 128 + col8 + 4];
            float vv[8] = {v0.x, v0.y, v0.z, v0.w, v1.x, v1.y, v1.z, v1.w};
#pragma unroll
            for (int j = 0; j < 8; j++) {
                oacc[0][j] += p0 * vv[j];
                oacc[1][j] += p1 * vv[j];
                oacc[2][j] += p2 * vv[j];
                oacc[3][j] += p3 * vv[j];
            }
        }
    }

    float* op = o + ((size_t)(b * SEQ + q0)) * DMODEL + h * DHEAD;
#pragma unroll
    for (int i = 0; i < 4; i++) {
        float inv = 1.f / lrow[row4 + i];
        float4 c0 = make_float4(oacc[i][0]*inv, oacc[i][1]*inv, oacc[i][2]*inv, oacc[i][3]*inv);
        float4 c1 = make_float4(oacc[i][4]*inv, oacc[i][5]*inv, oacc[i][6]*inv, oacc[i][7]*inv);
        size_t off = (size_t)(row4 + i) * DMODEL + col8;
        *(float4*)&op[off]     = c0;
        *(float4*)&op[off + 4] = c1;
    }
}

// ============================================================================
extern "C" void kernel_launch(void* const* d_in, const int* in_sizes, int n_in,
                              void* d_out, int out_size)
{
    const float* x  = (const float*)d_in[0];
    const float* rc = (const float*)d_in[1];
    const float* rs = (const float*)d_in[2];
    const float* Wq = (const float*)d_in[3];
    const float* Wk = (const float*)d_in[4];
    const float* Wv = (const float*)d_in[5];
    const float* Wo = (const float*)d_in[6];
    float* out = (float*)d_out;

    float *q, *k, *v, *att;
    cudaGetSymbolAddress((void**)&q,   g_q);
    cudaGetSymbolAddress((void**)&k,   g_k);
    cudaGetSymbolAddress((void**)&v,   g_v);
    cudaGetSymbolAddress((void**)&att, g_att);

    __nv_bfloat16 *xhi, *xlo, *wqhi, *wqlo, *wkhi, *wklo, *wvhi, *wvlo, *wohi, *wolo, *atthi, *attlo;
    cudaGetSymbolAddress((void**)&xhi,  g_xhi);   cudaGetSymbolAddress((void**)&xlo,  g_xlo);
    cudaGetSymbolAddress((void**)&wqhi, g_wqhi);  cudaGetSymbolAddress((void**)&wqlo, g_wqlo);
    cudaGetSymbolAddress((void**)&wkhi, g_wkhi);  cudaGetSymbolAddress((void**)&wklo, g_wklo);
    cudaGetSymbolAddress((void**)&wvhi, g_wvhi);  cudaGetSymbolAddress((void**)&wvlo, g_wvlo);
    cudaGetSymbolAddress((void**)&wohi, g_wohi);  cudaGetSymbolAddress((void**)&wolo, g_wolo);
    cudaGetSymbolAddress((void**)&atthi, g_atthi); cudaGetSymbolAddress((void**)&attlo, g_attlo);

    cudaFuncSetAttribute(attn_kernel, cudaFuncAttributeMaxDynamicSharedMemorySize, ATT_SMEM_BYTES);
    cudaFuncSetAttribute(gemm_mma,    cudaFuncAttributeMaxDynamicSharedMemorySize, GEMM_SMEM);

    const int npx = MROWS * DMODEL / 2;   // pairs for activations
    const int npw = DMODEL * DMODEL / 2;  // pairs for weights
    pack_split<<<(npx + 255) / 256, 256>>>(x,  (uint32_t*)xhi,  (uint32_t*)xlo,  npx);
    pack_split<<<(npw + 255) / 256, 256>>>(Wq, (uint32_t*)wqhi, (uint32_t*)wqlo, npw);
    pack_split<<<(npw + 255) / 256, 256>>>(Wk, (uint32_t*)wkhi, (uint32_t*)wklo, npw);
    pack_split<<<(npw + 255) / 256, 256>>>(Wv, (uint32_t*)wvhi, (uint32_t*)wvlo, npw);
    pack_split<<<(npw + 255) / 256, 256>>>(Wo, (uint32_t*)wohi, (uint32_t*)wolo, npw);

    dim3 gg(DMODEL / 128, MROWS / 128);   // (16, 32)
    gemm_mma<<<gg, 256, GEMM_SMEM>>>(xhi, xlo, wqhi, wqlo, q);
    gemm_mma<<<gg, 256, GEMM_SMEM>>>(xhi, xlo, wkhi, wklo, k);
    gemm_mma<<<gg, 256, GEMM_SMEM>>>(xhi, xlo, wvhi, wvlo, v);

    int rope_threads = BATCH * SEQ * NHEADS * 64;
    rope_kernel<<<(rope_threads + 255) / 256, 256>>>(q, k, rc, rs);

    attn_kernel<<<dim3(SEQ / 64, NHEADS, BATCH), 256, ATT_SMEM_BYTES>>>(q, k, v, att);

    pack_split<<<(npx + 255) / 256, 256>>>(att, (uint32_t*)atthi, (uint32_t*)attlo, npx);
    gemm_mma<<<gg, 256, GEMM_SMEM>>>(atthi, attlo, wohi, wolo, out);
}

// round 5
// speedup vs baseline: 3.1365x; 2.1808x over previous
#include <cuda_runtime.h>
#include <cuda_bf16.h>
#include <math.h>
#include <stdint.h>

// Problem constants
#define BATCH 2
#define SEQ   2048
#define DMODEL 2048
#define NHEADS 16
#define DHEAD 128
#define MROWS (BATCH*SEQ)          // 4096
#define KDIM  DMODEL

// -------------------- scratch (static device globals; no allocation) ------
__device__ float g_q[MROWS * DMODEL];
__device__ float g_k[MROWS * DMODEL];
__device__ float g_v[MROWS * DMODEL];
__device__ float g_att[MROWS * DMODEL];

// bf16 hi/lo planes, plain row-major
__device__ __align__(16) __nv_bfloat16 g_xhi[MROWS * DMODEL];
__device__ __align__(16) __nv_bfloat16 g_xlo[MROWS * DMODEL];
__device__ __align__(16) __nv_bfloat16 g_wqhi[DMODEL * DMODEL];
__device__ __align__(16) __nv_bfloat16 g_wqlo[DMODEL * DMODEL];
__device__ __align__(16) __nv_bfloat16 g_wkhi[DMODEL * DMODEL];
__device__ __align__(16) __nv_bfloat16 g_wklo[DMODEL * DMODEL];
__device__ __align__(16) __nv_bfloat16 g_wvhi[DMODEL * DMODEL];
__device__ __align__(16) __nv_bfloat16 g_wvlo[DMODEL * DMODEL];
__device__ __align__(16) __nv_bfloat16 g_wohi[DMODEL * DMODEL];
__device__ __align__(16) __nv_bfloat16 g_wolo[DMODEL * DMODEL];
__device__ __align__(16) __nv_bfloat16 g_atthi[MROWS * DMODEL];
__device__ __align__(16) __nv_bfloat16 g_attlo[MROWS * DMODEL];
// K/V planes for attention (post-rope)
__device__ __align__(16) __nv_bfloat16 g_khi[MROWS * DMODEL];
__device__ __align__(16) __nv_bfloat16 g_klo[MROWS * DMODEL];
__device__ __align__(16) __nv_bfloat16 g_vhi[MROWS * DMODEL];
__device__ __align__(16) __nv_bfloat16 g_vlo[MROWS * DMODEL];

// ============================ PTX helpers (sm_80-baseline only) ============
__device__ __forceinline__ uint32_t smem_u32(const void* p) {
    uint32_t a;
    asm("{ .reg .u64 t; cvta.to.shared.u64 t, %1; cvt.u32.u64 %0, t; }" : "=r"(a) : "l"(p));
    return a;
}
#define CP_ASYNC16(dst, src) \
    asm volatile("cp.async.cg.shared.global [%0], [%1], 16;" :: "r"(dst), "l"(src))
#define CP_COMMIT() asm volatile("cp.async.commit_group;" ::: "memory")
#define CP_WAIT(n)  asm volatile("cp.async.wait_group %0;" :: "n"(n) : "memory")

#define LDSM4(r0, r1, r2, r3, addr) \
    asm volatile("ldmatrix.sync.aligned.m8n8.x4.shared.b16 {%0,%1,%2,%3}, [%4];" \
        : "=r"(r0), "=r"(r1), "=r"(r2), "=r"(r3) : "r"(addr))
#define LDSM4T(r0, r1, r2, r3, addr) \
    asm volatile("ldmatrix.sync.aligned.m8n8.x4.trans.shared.b16 {%0,%1,%2,%3}, [%4];" \
        : "=r"(r0), "=r"(r1), "=r"(r2), "=r"(r3) : "r"(addr))

#define MMA16816(c, a, b) \
    asm volatile("mma.sync.aligned.m16n8k16.row.col.f32.bf16.bf16.f32 " \
        "{%0,%1,%2,%3},{%4,%5,%6,%7},{%8,%9},{%0,%1,%2,%3};" \
        : "+f"((c)[0]), "+f"((c)[1]), "+f"((c)[2]), "+f"((c)[3]) \
        : "r"((a)[0]), "r"((a)[1]), "r"((a)[2]), "r"((a)[3]), "r"((b)[0]), "r"((b)[1]))

__device__ __forceinline__ uint32_t pk_hi(float a, float b) {
    return (uint32_t)__bfloat16_as_ushort(__float2bfloat16(a)) |
           ((uint32_t)__bfloat16_as_ushort(__float2bfloat16(b)) << 16);
}

// ============================================================================
// pack_split: fp32 row-major -> bf16 hi/lo planes (plain row-major).
// ============================================================================
__global__ __launch_bounds__(256)
void pack_split(const float* __restrict__ src,
                uint32_t* __restrict__ hi, uint32_t* __restrict__ lo, int npairs)
{
    int i = blockIdx.x * 256 + threadIdx.x;
    if (i >= npairs) return;
    float2 v = ((const float2*)src)[i];
    __nv_bfloat16 h0 = __float2bfloat16(v.x);
    __nv_bfloat16 h1 = __float2bfloat16(v.y);
    __nv_bfloat16 l0 = __float2bfloat16(v.x - __bfloat162float(h0));
    __nv_bfloat16 l1 = __float2bfloat16(v.y - __bfloat162float(h1));
    hi[i] = (uint32_t)__bfloat16_as_ushort(h0) | ((uint32_t)__bfloat16_as_ushort(h1) << 16);
    lo[i] = (uint32_t)__bfloat16_as_ushort(l0) | ((uint32_t)__bfloat16_as_ushort(l1) << 16);
}

// ============================================================================
// gemm_mma (unchanged): C = A @ B^T, hi/lo split, 3 products.
// ============================================================================
#define BKD 32
#define TILE_B   (128 * BKD * 2)
#define STAGE_B  (4 * TILE_B)
#define GSTAGES  3
#define GEMM_SMEM (GSTAGES * STAGE_B)

__global__ __launch_bounds__(256)
void gemm_mma(const __nv_bfloat16* __restrict__ Ahi, const __nv_bfloat16* __restrict__ Alo,
              const __nv_bfloat16* __restrict__ Bhi, const __nv_bfloat16* __restrict__ Blo,
              float* __restrict__ C)
{
    extern __shared__ char smc[];
    const uint32_t sb = smem_u32(smc);

    const int tid  = threadIdx.x;
    const int lane = tid & 31;
    const int wid  = tid >> 5;
    const int wm   = wid & 1;
    const int wn   = wid >> 1;
    const int m0   = blockIdx.y * 128;
    const int n0   = blockIdx.x * 128;

    const int r1 = tid >> 2, c1 = tid & 3;
    const int r2 = (tid + 256) >> 2, c2 = (tid + 256) & 3;
    const uint32_t d1 = (uint32_t)(r1 * 64 + ((c1 ^ ((r1 >> 1) & 3)) * 16));
    const uint32_t d2 = (uint32_t)(r2 * 64 + ((c2 ^ ((r2 >> 1) & 3)) * 16));

    const __nv_bfloat16* srcA[2] = { Ahi + (size_t)m0 * KDIM, Alo + (size_t)m0 * KDIM };
    const __nv_bfloat16* srcB[2] = { Bhi + (size_t)n0 * KDIM, Blo + (size_t)n0 * KDIM };

    auto load_stage = [&](int s, int kb) {
        uint32_t base = sb + s * STAGE_B;
        int koff = kb * BKD;
#pragma unroll
        for (int t = 0; t < 2; t++) {
            CP_ASYNC16(base + t * TILE_B + d1, srcA[t] + (size_t)r1 * KDIM + koff + c1 * 8);
            CP_ASYNC16(base + t * TILE_B + d2, srcA[t] + (size_t)r2 * KDIM + koff + c2 * 8);
            CP_ASYNC16(base + (2 + t) * TILE_B + d1, srcB[t] + (size_t)r1 * KDIM + koff + c1 * 8);
            CP_ASYNC16(base + (2 + t) * TILE_B + d2, srcB[t] + (size_t)r2 * KDIM + koff + c2 * 8);
        }
    };

    float acc[4][4][4];
#pragma unroll
    for (int i = 0; i < 4; i++)
#pragma unroll
        for (int j = 0; j < 4; j++)
#pragma unroll
            for (int r = 0; r < 4; r++) acc[i][j][r] = 0.f;

    load_stage(0, 0); CP_COMMIT();
    load_stage(1, 1); CP_COMMIT();

    const int arow = wm * 64 + (lane & 15);
    const int bnrow = wn * 32 + (lane & 15);
    const int lhalf = lane >> 4;

    const int NKB = KDIM / BKD;
    for (int kc = 0; kc < NKB; kc++) {
        CP_WAIT(1);
        __syncthreads();
        if (kc + 2 < NKB) load_stage((kc + 2) % GSTAGES, kc + 2);
        CP_COMMIT();

        uint32_t base = sb + (kc % GSTAGES) * STAGE_B;
        uint32_t aHb = base, aLb = base + TILE_B, bHb = base + 2 * TILE_B, bLb = base + 3 * TILE_B;

#pragma unroll
        for (int ks = 0; ks < 2; ks++) {
            uint32_t ah[4][4], al[4][4], bh[4][2], bl[4][2];
#pragma unroll
            for (int i = 0; i < 4; i++) {
                int row = arow + i * 16;
                uint32_t off = (uint32_t)(row * 64 + (((ks * 2 + lhalf) ^ ((row >> 1) & 3)) * 16));
                LDSM4(ah[i][0], ah[i][1], ah[i][2], ah[i][3], aHb + off);
                LDSM4(al[i][0], al[i][1], al[i][2], al[i][3], aLb + off);
            }
#pragma unroll
            for (int jp = 0; jp < 2; jp++) {
                int row = bnrow + jp * 16;
                uint32_t off = (uint32_t)(row * 64 + (((ks * 2 + lhalf) ^ ((row >> 1) & 3)) * 16));
                uint32_t r0, r1_, r2_, r3_;
                LDSM4(r0, r1_, r2_, r3_, bHb + off);
                bh[2 * jp][0] = r0;  bh[2 * jp][1] = r2_;
                bh[2 * jp + 1][0] = r1_; bh[2 * jp + 1][1] = r3_;
                LDSM4(r0, r1_, r2_, r3_, bLb + off);
                bl[2 * jp][0] = r0;  bl[2 * jp][1] = r2_;
                bl[2 * jp + 1][0] = r1_; bl[2 * jp + 1][1] = r3_;
            }
#pragma unroll
            for (int i = 0; i < 4; i++)
#pragma unroll
                for (int j = 0; j < 4; j++) {
                    MMA16816(acc[i][j], ah[i], bh[j]);
                    MMA16816(acc[i][j], ah[i], bl[j]);
                    MMA16816(acc[i][j], al[i], bh[j]);
                }
        }
    }

#pragma unroll
    for (int i = 0; i < 4; i++) {
#pragma unroll
        for (int j = 0; j < 4; j++) {
            int m = m0 + wm * 64 + i * 16 + (lane >> 2);
            int n = n0 + wn * 32 + j * 8 + (lane & 3) * 2;
            *(float2*)&C[(size_t)m * DMODEL + n]       = make_float2(acc[i][j][0], acc[i][j][1]);
            *(float2*)&C[(size_t)(m + 8) * DMODEL + n] = make_float2(acc[i][j][2], acc[i][j][3]);
        }
    }
}

// ============================================================================
// RoPE (in-place on q and k)
// ============================================================================
__global__ __launch_bounds__(256)
void rope_kernel(float* __restrict__ q, float* __restrict__ k,
                 const float* __restrict__ rc, const float* __restrict__ rs)
{
    int idx = blockIdx.x * 256 + threadIdx.x;
    const int total = BATCH * SEQ * NHEADS * 64;
    if (idx >= total) return;
    int d = idx & 63;
    int h = (idx >> 6) & (NHEADS - 1);
    int s = (idx >> 10) & (SEQ - 1);
    int b = idx >> 21;
    size_t base = ((size_t)(b * SEQ + s)) * DMODEL + h * DHEAD;
    float c0 = rc[s * DHEAD + d],      s0 = rs[s * DHEAD + d];
    float c1 = rc[s * DHEAD + 64 + d], s1 = rs[s * DHEAD + 64 + d];

    float q0 = q[base + d], q1 = q[base + 64 + d];
    q[base + d]      = q0 * c0 - q1 * s0;
    q[base + 64 + d] = q1 * c1 + q0 * s1;

    float k0 = k[base + d], k1 = k[base + 64 + d];
    k[base + d]      = k0 * c0 - k1 * s0;
    k[base + 64 + d] = k1 * c1 + k0 * s1;
}

// ============================================================================
// attn_tc: flash attention on mma.sync bf16 hi/lo.
// CTA: 128 q-rows (8 warps x 16 rows, each warp owns all 64 key cols).
// PV FIX (R5): n-block loop covers all 8 blocks (dh 0..127), not 4.
// ============================================================================
#define NKT (SEQ/64)
#define ATT_PLANE_B 16384
#define ATT_STAGE_B (4*ATT_PLANE_B)
#define ATT_Q_B     65536
#define ATT_TC_SMEM (ATT_Q_B + 2*ATT_STAGE_B)   // 196608

__global__ __launch_bounds__(256, 1)
void attn_tc(const float* __restrict__ q,
             const __nv_bfloat16* __restrict__ khi, const __nv_bfloat16* __restrict__ klo,
             const __nv_bfloat16* __restrict__ vhi, const __nv_bfloat16* __restrict__ vlo,
             float* __restrict__ o)
{
    extern __shared__ char smc[];
    const uint32_t sb = smem_u32(smc);
    const uint32_t QH = sb, QL = sb + 32768;
    const uint32_t ST = sb + ATT_Q_B;

    const int tid = threadIdx.x;
    const int lane = tid & 31;
    const int wid = tid >> 5;
    const int b = blockIdx.z, h = blockIdx.y;
    const int q0 = blockIdx.x * 128;
    const int wrow = wid * 16;
    const float scale = 0.088388347648318447f;   // 1/sqrt(128)

    // ---- fill Q smem (scaled, hi/lo split, swizzled) ----
    const float* qp = q + ((size_t)(b * SEQ + q0)) * DMODEL + h * DHEAD;
#pragma unroll
    for (int i = 0; i < 8; i++) {
        int idx = tid + i * 256;          // 0..2047
        int row = idx >> 4, ch = idx & 15;
        const float* s = qp + (size_t)row * DMODEL + ch * 8;
        float4 f0 = *(const float4*)s;
        float4 f1 = *(const float4*)(s + 4);
        float v[8] = { f0.x*scale, f0.y*scale, f0.z*scale, f0.w*scale,
                       f1.x*scale, f1.y*scale, f1.z*scale, f1.w*scale };
        uint32_t hp[4], lp[4];
#pragma unroll
        for (int p = 0; p < 4; p++) {
            float a = v[2*p], c = v[2*p+1];
            __nv_bfloat16 ha = __float2bfloat16(a), hc = __float2bfloat16(c);
            hp[p] = (uint32_t)__bfloat16_as_ushort(ha) | ((uint32_t)__bfloat16_as_ushort(hc) << 16);
            lp[p] = pk_hi(a - __bfloat162float(ha), c - __bfloat162float(hc));
        }
        uint32_t off = (uint32_t)(row * 256 + ((ch ^ (row & 15)) << 4));
        *(uint4*)(smc + off)         = make_uint4(hp[0], hp[1], hp[2], hp[3]);
        *(uint4*)(smc + 32768 + off) = make_uint4(lp[0], lp[1], lp[2], lp[3]);
    }

    // ---- K/V stage loader ----
    const __nv_bfloat16* pl[4] = { khi, klo, vhi, vlo };
    auto load_kv = [&](int st, int kt) {
        uint32_t base = ST + st * ATT_STAGE_B;
#pragma unroll
        for (int i = 0; i < 16; i++) {
            int idx = tid + i * 256;           // 0..4095
            int p = idx >> 10;                 // plane
            int c = idx & 1023;
            int row = c >> 4, ch = c & 15;
            const __nv_bfloat16* src = pl[p] +
                ((size_t)(b * SEQ + kt * 64 + row)) * DMODEL + h * DHEAD + ch * 8;
            uint32_t dst = base + p * ATT_PLANE_B + row * 256 + ((ch ^ (row & 15)) << 4);
            CP_ASYNC16(dst, src);
        }
    };

    float o_[16][4];
#pragma unroll
    for (int n = 0; n < 16; n++)
#pragma unroll
        for (int r = 0; r < 4; r++) o_[n][r] = 0.f;
    float m_a = -3.0e38f, m_b = -3.0e38f, l_a = 0.f, l_b = 0.f;

    load_kv(0, 0); CP_COMMIT();
    load_kv(1, 1); CP_COMMIT();

    const int qrow = wrow + (lane & 15);
    const int lh = lane >> 4;

    for (int kt = 0; kt < NKT; kt++) {
        CP_WAIT(1);
        __syncthreads();
        uint32_t bs = ST + (kt & 1) * ATT_STAGE_B;

        // ---- scores S[16x64] = Qtile @ Ktile^T (hi/lo, 3 products) ----
        float s[8][4];
#pragma unroll
        for (int j = 0; j < 8; j++)
#pragma unroll
            for (int r = 0; r < 4; r++) s[j][r] = 0.f;

#pragma unroll
        for (int ks = 0; ks < 8; ks++) {
            uint32_t qoff = (uint32_t)(qrow * 256 + (((ks * 2 + lh) ^ (qrow & 15)) << 4));
            uint32_t ah[4], al[4];
            LDSM4(ah[0], ah[1], ah[2], ah[3], QH + qoff);
            LDSM4(al[0], al[1], al[2], al[3], QL + qoff);
#pragma unroll
            for (int nb = 0; nb < 4; nb++) {
                int krow = nb * 16 + (lane & 15);
                uint32_t koff = (uint32_t)(krow * 256 + (((ks * 2 + lh) ^ (krow & 15)) << 4));
                uint32_t h0, h1, h2, h3, l0, l1, l2, l3;
                LDSM4(h0, h1, h2, h3, bs + koff);
                LDSM4(l0, l1, l2, l3, bs + ATT_PLANE_B + koff);
                uint32_t bh0[2] = { h0, h2 }, bh1[2] = { h1, h3 };
                uint32_t bl0[2] = { l0, l2 }, bl1[2] = { l1, l3 };
                MMA16816(s[2*nb],   ah, bh0); MMA16816(s[2*nb],   ah, bl0); MMA16816(s[2*nb],   al, bh0);
                MMA16816(s[2*nb+1], ah, bh1); MMA16816(s[2*nb+1], ah, bl1); MMA16816(s[2*nb+1], al, bh1);
            }
        }

        // ---- online softmax (rows lane>>2 and +8) ----
        float mla = -3.0e38f, mlb = -3.0e38f;
#pragma unroll
        for (int j = 0; j < 8; j++) {
            mla = fmaxf(mla, fmaxf(s[j][0], s[j][1]));
            mlb = fmaxf(mlb, fmaxf(s[j][2], s[j][3]));
        }
        mla = fmaxf(mla, __shfl_xor_sync(0xffffffffu, mla, 1));
        mla = fmaxf(mla, __shfl_xor_sync(0xffffffffu, mla, 2));
        mlb = fmaxf(mlb, __shfl_xor_sync(0xffffffffu, mlb, 1));
        mlb = fmaxf(mlb, __shfl_xor_sync(0xffffffffu, mlb, 2));
        float mna = fmaxf(m_a, mla), mnb = fmaxf(m_b, mlb);
        float aa = __expf(m_a - mna), ab = __expf(m_b - mnb);

        uint32_t pAh[8], pBh[8], pAl[8], pBl[8];
        float sa = 0.f, sb2 = 0.f;
#pragma unroll
        for (int j = 0; j < 8; j++) {
            float p0 = __expf(s[j][0] - mna), p1 = __expf(s[j][1] - mna);
            float p2 = __expf(s[j][2] - mnb), p3 = __expf(s[j][3] - mnb);
            sa += p0 + p1; sb2 += p2 + p3;
            __nv_bfloat16 h0 = __float2bfloat16(p0), h1 = __float2bfloat16(p1);
            __nv_bfloat16 h2 = __float2bfloat16(p2), h3 = __float2bfloat16(p3);
            pAh[j] = (uint32_t)__bfloat16_as_ushort(h0) | ((uint32_t)__bfloat16_as_ushort(h1) << 16);
            pBh[j] = (uint32_t)__bfloat16_as_ushort(h2) | ((uint32_t)__bfloat16_as_ushort(h3) << 16);
            pAl[j] = pk_hi(p0 - __bfloat162float(h0), p1 - __bfloat162float(h1));
            pBl[j] = pk_hi(p2 - __bfloat162float(h2), p3 - __bfloat162float(h3));
        }
        sa  += __shfl_xor_sync(0xffffffffu, sa, 1);
        sa  += __shfl_xor_sync(0xffffffffu, sa, 2);
        sb2 += __shfl_xor_sync(0xffffffffu, sb2, 1);
        sb2 += __shfl_xor_sync(0xffffffffu, sb2, 2);
        m_a = mna; m_b = mnb;
        l_a = l_a * aa + sa; l_b = l_b * ab + sb2;

#pragma unroll
        for (int n = 0; n < 16; n++) {
            o_[n][0] *= aa; o_[n][1] *= aa; o_[n][2] *= ab; o_[n][3] *= ab;
        }

        // ---- PV: O += P @ V (hi/lo, 3 products), V via ldmatrix.trans ----
        // FIXED: nb runs over all 8 n-blocks (dh 0..127).
#pragma unroll
        for (int kp = 0; kp < 4; kp++) {
            uint32_t ah4[4] = { pAh[2*kp], pBh[2*kp], pAh[2*kp+1], pBh[2*kp+1] };
            uint32_t al4[4] = { pAl[2*kp], pBl[2*kp], pAl[2*kp+1], pBl[2*kp+1] };
            int vrow = kp * 16 + (lane & 15);
#pragma unroll
            for (int nb = 0; nb < 8; nb++) {
                uint32_t ch = (uint32_t)(nb * 2 + lh);
                uint32_t voff = (uint32_t)(vrow * 256 + ((ch ^ (vrow & 15)) << 4));
                uint32_t h0, h1, h2, h3, l0, l1, l2, l3;
                LDSM4T(h0, h1, h2, h3, bs + 2 * ATT_PLANE_B + voff);
                LDSM4T(l0, l1, l2, l3, bs + 3 * ATT_PLANE_B + voff);
                uint32_t bh0[2] = { h0, h1 }, bh1[2] = { h2, h3 };
                uint32_t bl0[2] = { l0, l1 }, bl1[2] = { l2, l3 };
                MMA16816(o_[2*nb],   ah4, bh0); MMA16816(o_[2*nb],   ah4, bl0); MMA16816(o_[2*nb],   al4, bh0);
                MMA16816(o_[2*nb+1], ah4, bh1); MMA16816(o_[2*nb+1], ah4, bl1); MMA16816(o_[2*nb+1], al4, bh1);
            }
        }

        __syncthreads();
        if (kt + 2 < NKT) { load_kv(kt & 1, kt + 2); CP_COMMIT(); }
    }

    // ---- epilogue ----
    float ia = 1.f / l_a, ib = 1.f / l_b;
    float* op = o + ((size_t)(b * SEQ + q0 + wrow + (lane >> 2))) * DMODEL
                  + h * DHEAD + 2 * (lane & 3);
#pragma unroll
    for (int n = 0; n < 16; n++) {
        *(float2*)&op[n * 8] = make_float2(o_[n][0] * ia, o_[n][1] * ia);
        *(float2*)&op[(size_t)8 * DMODEL + n * 8] = make_float2(o_[n][2] * ib, o_[n][3] * ib);
    }
}

// ============================================================================
extern "C" void kernel_launch(void* const* d_in, const int* in_sizes, int n_in,
                              void* d_out, int out_size)
{
    const float* x  = (const float*)d_in[0];
    const float* rc = (const float*)d_in[1];
    const float* rs = (const float*)d_in[2];
    const float* Wq = (const float*)d_in[3];
    const float* Wk = (const float*)d_in[4];
    const float* Wv = (const float*)d_in[5];
    const float* Wo = (const float*)d_in[6];
    float* out = (float*)d_out;

    float *q, *k, *v, *att;
    cudaGetSymbolAddress((void**)&q,   g_q);
    cudaGetSymbolAddress((void**)&k,   g_k);
    cudaGetSymbolAddress((void**)&v,   g_v);
    cudaGetSymbolAddress((void**)&att, g_att);

    __nv_bfloat16 *xhi, *xlo, *wqhi, *wqlo, *wkhi, *wklo, *wvhi, *wvlo, *wohi, *wolo, *atthi, *attlo;
    __nv_bfloat16 *khi, *klo, *vhi, *vlo;
    cudaGetSymbolAddress((void**)&xhi,  g_xhi);   cudaGetSymbolAddress((void**)&xlo,  g_xlo);
    cudaGetSymbolAddress((void**)&wqhi, g_wqhi);  cudaGetSymbolAddress((void**)&wqlo, g_wqlo);
    cudaGetSymbolAddress((void**)&wkhi, g_wkhi);  cudaGetSymbolAddress((void**)&wklo, g_wklo);
    cudaGetSymbolAddress((void**)&wvhi, g_wvhi);  cudaGetSymbolAddress((void**)&wvlo, g_wvlo);
    cudaGetSymbolAddress((void**)&wohi, g_wohi);  cudaGetSymbolAddress((void**)&wolo, g_wolo);
    cudaGetSymbolAddress((void**)&atthi, g_atthi); cudaGetSymbolAddress((void**)&attlo, g_attlo);
    cudaGetSymbolAddress((void**)&khi, g_khi);    cudaGetSymbolAddress((void**)&klo, g_klo);
    cudaGetSymbolAddress((void**)&vhi, g_vhi);    cudaGetSymbolAddress((void**)&vlo, g_vlo);

    cudaFuncSetAttribute(gemm_mma, cudaFuncAttributeMaxDynamicSharedMemorySize, GEMM_SMEM);
    cudaFuncSetAttribute(attn_tc,  cudaFuncAttributeMaxDynamicSharedMemorySize, ATT_TC_SMEM);

    const int npx = MROWS * DMODEL / 2;
    const int npw = DMODEL * DMODEL / 2;
    pack_split<<<(npx + 255) / 256, 256>>>(x,  (uint32_t*)xhi,  (uint32_t*)xlo,  npx);
    pack_split<<<(npw + 255) / 256, 256>>>(Wq, (uint32_t*)wqhi, (uint32_t*)wqlo, npw);
    pack_split<<<(npw + 255) / 256, 256>>>(Wk, (uint32_t*)wkhi, (uint32_t*)wklo, npw);
    pack_split<<<(npw + 255) / 256, 256>>>(Wv, (uint32_t*)wvhi, (uint32_t*)wvlo, npw);
    pack_split<<<(npw + 255) / 256, 256>>>(Wo, (uint32_t*)wohi, (uint32_t*)wolo, npw);

    dim3 gg(DMODEL / 128, MROWS / 128);
    gemm_mma<<<gg, 256, GEMM_SMEM>>>(xhi, xlo, wqhi, wqlo, q);
    gemm_mma<<<gg, 256, GEMM_SMEM>>>(xhi, xlo, wkhi, wklo, k);
    gemm_mma<<<gg, 256, GEMM_SMEM>>>(xhi, xlo, wvhi, wvlo, v);

    int rope_threads = BATCH * SEQ * NHEADS * 64;
    rope_kernel<<<(rope_threads + 255) / 256, 256>>>(q, k, rc, rs);

    // pack K and V (post-rope) for the tensor-core attention
    pack_split<<<(npx + 255) / 256, 256>>>(k, (uint32_t*)khi, (uint32_t*)klo, npx);
    pack_split<<<(npx + 255) / 256, 256>>>(v, (uint32_t*)vhi, (uint32_t*)vlo, npx);

    attn_tc<<<dim3(SEQ / 128, NHEADS, BATCH), 256, ATT_TC_SMEM>>>(q, khi, klo, vhi, vlo, att);

    pack_split<<<(npx + 255) / 256, 256>>>(att, (uint32_t*)atthi, (uint32_t*)attlo, npx);
    gemm_mma<<<gg, 256, GEMM_SMEM>>>(atthi, attlo, wohi, wolo, out);
}

// round 6
// speedup vs baseline: 3.2095x; 1.0233x over previous
#include <cuda_runtime.h>
#include <cuda_bf16.h>
#include <math.h>
#include <stdint.h>

// Problem constants
#define BATCH 2
#define SEQ   2048
#define DMODEL 2048
#define NHEADS 16
#define DHEAD 128
#define MROWS (BATCH*SEQ)          // 4096
#define KDIM  DMODEL

// -------------------- scratch (static device globals; no allocation) ------
__device__ float g_q[MROWS * DMODEL];
__device__ float g_k[MROWS * DMODEL];
__device__ float g_v[MROWS * DMODEL];

__device__ __align__(16) __nv_bfloat16 g_xhi[MROWS * DMODEL];
__device__ __align__(16) __nv_bfloat16 g_xlo[MROWS * DMODEL];
__device__ __align__(16) __nv_bfloat16 g_wqhi[DMODEL * DMODEL];
__device__ __align__(16) __nv_bfloat16 g_wqlo[DMODEL * DMODEL];
__device__ __align__(16) __nv_bfloat16 g_wkhi[DMODEL * DMODEL];
__device__ __align__(16) __nv_bfloat16 g_wklo[DMODEL * DMODEL];
__device__ __align__(16) __nv_bfloat16 g_wvhi[DMODEL * DMODEL];
__device__ __align__(16) __nv_bfloat16 g_wvlo[DMODEL * DMODEL];
__device__ __align__(16) __nv_bfloat16 g_wohi[DMODEL * DMODEL];
__device__ __align__(16) __nv_bfloat16 g_wolo[DMODEL * DMODEL];
__device__ __align__(16) __nv_bfloat16 g_atthi[MROWS * DMODEL];
__device__ __align__(16) __nv_bfloat16 g_attlo[MROWS * DMODEL];
__device__ __align__(16) __nv_bfloat16 g_khi[MROWS * DMODEL];
__device__ __align__(16) __nv_bfloat16 g_klo[MROWS * DMODEL];
__device__ __align__(16) __nv_bfloat16 g_vhi[MROWS * DMODEL];
__device__ __align__(16) __nv_bfloat16 g_vlo[MROWS * DMODEL];

// ============================ PTX helpers (sm_80-baseline only) ============
__device__ __forceinline__ uint32_t smem_u32(const void* p) {
    uint32_t a;
    asm("{ .reg .u64 t; cvta.to.shared.u64 t, %1; cvt.u32.u64 %0, t; }" : "=r"(a) : "l"(p));
    return a;
}
#define CP_ASYNC16(dst, src) \
    asm volatile("cp.async.cg.shared.global [%0], [%1], 16;" :: "r"(dst), "l"(src))
#define CP_COMMIT() asm volatile("cp.async.commit_group;" ::: "memory")
#define CP_WAIT(n)  asm volatile("cp.async.wait_group %0;" :: "n"(n) : "memory")

#define LDSM4(r0, r1, r2, r3, addr) \
    asm volatile("ldmatrix.sync.aligned.m8n8.x4.shared.b16 {%0,%1,%2,%3}, [%4];" \
        : "=r"(r0), "=r"(r1), "=r"(r2), "=r"(r3) : "r"(addr))
#define LDSM4T(r0, r1, r2, r3, addr) \
    asm volatile("ldmatrix.sync.aligned.m8n8.x4.trans.shared.b16 {%0,%1,%2,%3}, [%4];" \
        : "=r"(r0), "=r"(r1), "=r"(r2), "=r"(r3) : "r"(addr))

#define MMA16816(c, a, b) \
    asm volatile("mma.sync.aligned.m16n8k16.row.col.f32.bf16.bf16.f32 " \
        "{%0,%1,%2,%3},{%4,%5,%6,%7},{%8,%9},{%0,%1,%2,%3};" \
        : "+f"((c)[0]), "+f"((c)[1]), "+f"((c)[2]), "+f"((c)[3]) \
        : "r"((a)[0]), "r"((a)[1]), "r"((a)[2]), "r"((a)[3]), "r"((b)[0]), "r"((b)[1]))

__device__ __forceinline__ uint32_t pk_hi(float a, float b) {
    return (uint32_t)__bfloat16_as_ushort(__float2bfloat16(a)) |
           ((uint32_t)__bfloat16_as_ushort(__float2bfloat16(b)) << 16);
}
__device__ __forceinline__ void split1(float x, __nv_bfloat16& h, __nv_bfloat16& l) {
    h = __float2bfloat16(x);
    l = __float2bfloat16(x - __bfloat162float(h));
}

// ============================================================================
// pack_split: fp32 row-major -> bf16 hi/lo planes
// ============================================================================
__global__ __launch_bounds__(256)
void pack_split(const float* __restrict__ src,
                uint32_t* __restrict__ hi, uint32_t* __restrict__ lo, int npairs)
{
    int i = blockIdx.x * 256 + threadIdx.x;
    if (i >= npairs) return;
    float2 v = ((const float2*)src)[i];
    __nv_bfloat16 h0, l0, h1, l1;
    split1(v.x, h0, l0); split1(v.y, h1, l1);
    hi[i] = (uint32_t)__bfloat16_as_ushort(h0) | ((uint32_t)__bfloat16_as_ushort(h1) << 16);
    lo[i] = (uint32_t)__bfloat16_as_ushort(l0) | ((uint32_t)__bfloat16_as_ushort(l1) << 16);
}

// ============================================================================
// gemm_fused: C_z = A @ B_z^T, hi/lo split, 3 products.
// 512 threads / 16 warps (4m x 4n), warp tile 32x32, 3-stage cp.async.
// grid (16, 32, nmat): z selects B/C.
// ============================================================================
#define BKD 32
#define TILE_B   (128 * BKD * 2)
#define STAGE_B  (4 * TILE_B)
#define GSTAGES  3
#define GEMM_SMEM (GSTAGES * STAGE_B)

__global__ __launch_bounds__(512)
void gemm_fused(const __nv_bfloat16* __restrict__ Ahi, const __nv_bfloat16* __restrict__ Alo,
                const __nv_bfloat16* __restrict__ B0h, const __nv_bfloat16* __restrict__ B0l,
                const __nv_bfloat16* __restrict__ B1h, const __nv_bfloat16* __restrict__ B1l,
                const __nv_bfloat16* __restrict__ B2h, const __nv_bfloat16* __restrict__ B2l,
                float* __restrict__ C0, float* __restrict__ C1, float* __restrict__ C2)
{
    extern __shared__ char smc[];
    const uint32_t sb = smem_u32(smc);

    const int tid  = threadIdx.x;
    const int lane = tid & 31;
    const int wid  = tid >> 5;          // 0..15
    const int wm   = wid & 3;           // 4 m-tiles of 32
    const int wn   = wid >> 2;          // 4 n-tiles of 32
    const int m0   = blockIdx.y * 128;
    const int n0   = blockIdx.x * 128;
    const int z    = blockIdx.z;

    const __nv_bfloat16* Bhi = (z == 0) ? B0h : (z == 1) ? B1h : B2h;
    const __nv_bfloat16* Blo = (z == 0) ? B0l : (z == 1) ? B1l : B2l;
    float* C = (z == 0) ? C0 : (z == 1) ? C1 : C2;

    const int r1 = tid >> 2, c1 = tid & 3;
    const uint32_t d1 = (uint32_t)(r1 * 64 + ((c1 ^ ((r1 >> 1) & 3)) * 16));

    const __nv_bfloat16* srcA[2] = { Ahi + (size_t)m0 * KDIM, Alo + (size_t)m0 * KDIM };
    const __nv_bfloat16* srcB[2] = { Bhi + (size_t)n0 * KDIM, Blo + (size_t)n0 * KDIM };

    auto load_stage = [&](int s, int kb) {
        uint32_t base = sb + s * STAGE_B;
        int koff = kb * BKD;
#pragma unroll
        for (int t = 0; t < 2; t++) {
            CP_ASYNC16(base + t * TILE_B + d1,       srcA[t] + (size_t)r1 * KDIM + koff + c1 * 8);
            CP_ASYNC16(base + (2 + t) * TILE_B + d1, srcB[t] + (size_t)r1 * KDIM + koff + c1 * 8);
        }
    };

    float acc[2][4][4];
#pragma unroll
    for (int i = 0; i < 2; i++)
#pragma unroll
        for (int j = 0; j < 4; j++)
#pragma unroll
            for (int r = 0; r < 4; r++) acc[i][j][r] = 0.f;

    load_stage(0, 0); CP_COMMIT();
    load_stage(1, 1); CP_COMMIT();

    const int arow = wm * 32 + (lane & 15);
    const int bnrow = wn * 32 + (lane & 15);
    const int lhalf = lane >> 4;

    const int NKB = KDIM / BKD;
    for (int kc = 0; kc < NKB; kc++) {
        CP_WAIT(1);
        __syncthreads();
        if (kc + 2 < NKB) load_stage((kc + 2) % GSTAGES, kc + 2);
        CP_COMMIT();

        uint32_t base = sb + (kc % GSTAGES) * STAGE_B;
        uint32_t aHb = base, aLb = base + TILE_B, bHb = base + 2 * TILE_B, bLb = base + 3 * TILE_B;

#pragma unroll
        for (int ks = 0; ks < 2; ks++) {
            uint32_t ah[2][4], al[2][4], bh[4][2], bl[4][2];
#pragma unroll
            for (int i = 0; i < 2; i++) {
                int row = arow + i * 16;
                uint32_t off = (uint32_t)(row * 64 + (((ks * 2 + lhalf) ^ ((row >> 1) & 3)) * 16));
                LDSM4(ah[i][0], ah[i][1], ah[i][2], ah[i][3], aHb + off);
                LDSM4(al[i][0], al[i][1], al[i][2], al[i][3], aLb + off);
            }
#pragma unroll
            for (int jp = 0; jp < 2; jp++) {
                int row = bnrow + jp * 16;
                uint32_t off = (uint32_t)(row * 64 + (((ks * 2 + lhalf) ^ ((row >> 1) & 3)) * 16));
                uint32_t r0, r1_, r2_, r3_;
                LDSM4(r0, r1_, r2_, r3_, bHb + off);
                bh[2 * jp][0] = r0;  bh[2 * jp][1] = r2_;
                bh[2 * jp + 1][0] = r1_; bh[2 * jp + 1][1] = r3_;
                LDSM4(r0, r1_, r2_, r3_, bLb + off);
                bl[2 * jp][0] = r0;  bl[2 * jp][1] = r2_;
                bl[2 * jp + 1][0] = r1_; bl[2 * jp + 1][1] = r3_;
            }
#pragma unroll
            for (int i = 0; i < 2; i++)
#pragma unroll
                for (int j = 0; j < 4; j++) {
                    MMA16816(acc[i][j], ah[i], bh[j]);
                    MMA16816(acc[i][j], ah[i], bl[j]);
                    MMA16816(acc[i][j], al[i], bh[j]);
                }
        }
    }

#pragma unroll
    for (int i = 0; i < 2; i++) {
#pragma unroll
        for (int j = 0; j < 4; j++) {
            int m = m0 + wm * 32 + i * 16 + (lane >> 2);
            int n = n0 + wn * 32 + j * 8 + (lane & 3) * 2;
            *(float2*)&C[(size_t)m * DMODEL + n]       = make_float2(acc[i][j][0], acc[i][j][1]);
            *(float2*)&C[(size_t)(m + 8) * DMODEL + n] = make_float2(acc[i][j][2], acc[i][j][3]);
        }
    }
}

// ============================================================================
// rope_pack: rope q (in place, fp32) and k; emit khi/klo, vhi/vlo packed.
// One thread per (b,s,h,d<64).
// ============================================================================
__global__ __launch_bounds__(256)
void rope_pack(float* __restrict__ q, const float* __restrict__ k, const float* __restrict__ v,
               const float* __restrict__ rc, const float* __restrict__ rs,
               __nv_bfloat16* __restrict__ khi, __nv_bfloat16* __restrict__ klo,
               __nv_bfloat16* __restrict__ vhi, __nv_bfloat16* __restrict__ vlo)
{
    int idx = blockIdx.x * 256 + threadIdx.x;
    const int total = BATCH * SEQ * NHEADS * 64;
    if (idx >= total) return;
    int d = idx & 63;
    int h = (idx >> 6) & (NHEADS - 1);
    int s = (idx >> 10) & (SEQ - 1);
    int b = idx >> 21;
    size_t base = ((size_t)(b * SEQ + s)) * DMODEL + h * DHEAD;
    float c0 = rc[s * DHEAD + d],      s0 = rs[s * DHEAD + d];
    float c1 = rc[s * DHEAD + 64 + d], s1 = rs[s * DHEAD + 64 + d];

    float q0 = q[base + d], q1 = q[base + 64 + d];
    q[base + d]      = q0 * c0 - q1 * s0;
    q[base + 64 + d] = q1 * c1 + q0 * s1;

    float k0 = k[base + d], k1 = k[base + 64 + d];
    float kr0 = k0 * c0 - k1 * s0;
    float kr1 = k1 * c1 + k0 * s1;
    __nv_bfloat16 h0, l0;
    split1(kr0, h0, l0); khi[base + d] = h0;      klo[base + d] = l0;
    split1(kr1, h0, l0); khi[base + 64 + d] = h0; klo[base + 64 + d] = l0;

    float v0 = v[base + d], v1 = v[base + 64 + d];
    split1(v0, h0, l0); vhi[base + d] = h0;      vlo[base + d] = l0;
    split1(v1, h0, l0); vhi[base + 64 + d] = h0; vlo[base + 64 + d] = l0;
}

// ============================================================================
// attn_tc: flash attention on mma.sync bf16 hi/lo.
// Writes att hi/lo planes directly (no fp32 att array).
// ============================================================================
#define NKT (SEQ/64)
#define ATT_PLANE_B 16384
#define ATT_STAGE_B (4*ATT_PLANE_B)
#define ATT_Q_B     65536
#define ATT_TC_SMEM (ATT_Q_B + 2*ATT_STAGE_B)   // 196608

__global__ __launch_bounds__(256, 1)
void attn_tc(const float* __restrict__ q,
             const __nv_bfloat16* __restrict__ khi, const __nv_bfloat16* __restrict__ klo,
             const __nv_bfloat16* __restrict__ vhi, const __nv_bfloat16* __restrict__ vlo,
             __nv_bfloat16* __restrict__ ohi, __nv_bfloat16* __restrict__ olo)
{
    extern __shared__ char smc[];
    const uint32_t sb = smem_u32(smc);
    const uint32_t QH = sb, QL = sb + 32768;
    const uint32_t ST = sb + ATT_Q_B;

    const int tid = threadIdx.x;
    const int lane = tid & 31;
    const int wid = tid >> 5;
    const int b = blockIdx.z, h = blockIdx.y;
    const int q0 = blockIdx.x * 128;
    const int wrow = wid * 16;
    const float scale = 0.088388347648318447f;   // 1/sqrt(128)

    // ---- fill Q smem (scaled, hi/lo split, swizzled) ----
    const float* qp = q + ((size_t)(b * SEQ + q0)) * DMODEL + h * DHEAD;
#pragma unroll
    for (int i = 0; i < 8; i++) {
        int idx = tid + i * 256;
        int row = idx >> 4, ch = idx & 15;
        const float* s = qp + (size_t)row * DMODEL + ch * 8;
        float4 f0 = *(const float4*)s;
        float4 f1 = *(const float4*)(s + 4);
        float v[8] = { f0.x*scale, f0.y*scale, f0.z*scale, f0.w*scale,
                       f1.x*scale, f1.y*scale, f1.z*scale, f1.w*scale };
        uint32_t hp[4], lp[4];
#pragma unroll
        for (int p = 0; p < 4; p++) {
            float a = v[2*p], c = v[2*p+1];
            __nv_bfloat16 ha = __float2bfloat16(a), hc = __float2bfloat16(c);
            hp[p] = (uint32_t)__bfloat16_as_ushort(ha) | ((uint32_t)__bfloat16_as_ushort(hc) << 16);
            lp[p] = pk_hi(a - __bfloat162float(ha), c - __bfloat162float(hc));
        }
        uint32_t off = (uint32_t)(row * 256 + ((ch ^ (row & 15)) << 4));
        *(uint4*)(smc + off)         = make_uint4(hp[0], hp[1], hp[2], hp[3]);
        *(uint4*)(smc + 32768 + off) = make_uint4(lp[0], lp[1], lp[2], lp[3]);
    }

    const __nv_bfloat16* pl[4] = { khi, klo, vhi, vlo };
    auto load_kv = [&](int st, int kt) {
        uint32_t base = ST + st * ATT_STAGE_B;
#pragma unroll
        for (int i = 0; i < 16; i++) {
            int idx = tid + i * 256;
            int p = idx >> 10;
            int c = idx & 1023;
            int row = c >> 4, ch = c & 15;
            const __nv_bfloat16* src = pl[p] +
                ((size_t)(b * SEQ + kt * 64 + row)) * DMODEL + h * DHEAD + ch * 8;
            uint32_t dst = base + p * ATT_PLANE_B + row * 256 + ((ch ^ (row & 15)) << 4);
            CP_ASYNC16(dst, src);
        }
    };

    float o_[16][4];
#pragma unroll
    for (int n = 0; n < 16; n++)
#pragma unroll
        for (int r = 0; r < 4; r++) o_[n][r] = 0.f;
    float m_a = -3.0e38f, m_b = -3.0e38f, l_a = 0.f, l_b = 0.f;

    load_kv(0, 0); CP_COMMIT();
    load_kv(1, 1); CP_COMMIT();

    const int qrow = wrow + (lane & 15);
    const int lh = lane >> 4;

    for (int kt = 0; kt < NKT; kt++) {
        CP_WAIT(1);
        __syncthreads();
        uint32_t bs = ST + (kt & 1) * ATT_STAGE_B;

        float s[8][4];
#pragma unroll
        for (int j = 0; j < 8; j++)
#pragma unroll
            for (int r = 0; r < 4; r++) s[j][r] = 0.f;

#pragma unroll
        for (int ks = 0; ks < 8; ks++) {
            uint32_t qoff = (uint32_t)(qrow * 256 + (((ks * 2 + lh) ^ (qrow & 15)) << 4));
            uint32_t ah[4], al[4];
            LDSM4(ah[0], ah[1], ah[2], ah[3], QH + qoff);
            LDSM4(al[0], al[1], al[2], al[3], QL + qoff);
#pragma unroll
            for (int nb = 0; nb < 4; nb++) {
                int krow = nb * 16 + (lane & 15);
                uint32_t koff = (uint32_t)(krow * 256 + (((ks * 2 + lh) ^ (krow & 15)) << 4));
                uint32_t h0, h1, h2, h3, l0, l1, l2, l3;
                LDSM4(h0, h1, h2, h3, bs + koff);
                LDSM4(l0, l1, l2, l3, bs + ATT_PLANE_B + koff);
                uint32_t bh0[2] = { h0, h2 }, bh1[2] = { h1, h3 };
                uint32_t bl0[2] = { l0, l2 }, bl1[2] = { l1, l3 };
                MMA16816(s[2*nb],   ah, bh0); MMA16816(s[2*nb],   ah, bl0); MMA16816(s[2*nb],   al, bh0);
                MMA16816(s[2*nb+1], ah, bh1); MMA16816(s[2*nb+1], ah, bl1); MMA16816(s[2*nb+1], al, bh1);
            }
        }

        float mla = -3.0e38f, mlb = -3.0e38f;
#pragma unroll
        for (int j = 0; j < 8; j++) {
            mla = fmaxf(mla, fmaxf(s[j][0], s[j][1]));
            mlb = fmaxf(mlb, fmaxf(s[j][2], s[j][3]));
        }
        mla = fmaxf(mla, __shfl_xor_sync(0xffffffffu, mla, 1));
        mla = fmaxf(mla, __shfl_xor_sync(0xffffffffu, mla, 2));
        mlb = fmaxf(mlb, __shfl_xor_sync(0xffffffffu, mlb, 1));
        mlb = fmaxf(mlb, __shfl_xor_sync(0xffffffffu, mlb, 2));
        float mna = fmaxf(m_a, mla), mnb = fmaxf(m_b, mlb);
        float aa = __expf(m_a - mna), ab = __expf(m_b - mnb);

        uint32_t pAh[8], pBh[8], pAl[8], pBl[8];
        float sa = 0.f, sb2 = 0.f;
#pragma unroll
        for (int j = 0; j < 8; j++) {
            float p0 = __expf(s[j][0] - mna), p1 = __expf(s[j][1] - mna);
            float p2 = __expf(s[j][2] - mnb), p3 = __expf(s[j][3] - mnb);
            sa += p0 + p1; sb2 += p2 + p3;
            __nv_bfloat16 h0 = __float2bfloat16(p0), h1 = __float2bfloat16(p1);
            __nv_bfloat16 h2 = __float2bfloat16(p2), h3 = __float2bfloat16(p3);
            pAh[j] = (uint32_t)__bfloat16_as_ushort(h0) | ((uint32_t)__bfloat16_as_ushort(h1) << 16);
            pBh[j] = (uint32_t)__bfloat16_as_ushort(h2) | ((uint32_t)__bfloat16_as_ushort(h3) << 16);
            pAl[j] = pk_hi(p0 - __bfloat162float(h0), p1 - __bfloat162float(h1));
            pBl[j] = pk_hi(p2 - __bfloat162float(h2), p3 - __bfloat162float(h3));
        }
        sa  += __shfl_xor_sync(0xffffffffu, sa, 1);
        sa  += __shfl_xor_sync(0xffffffffu, sa, 2);
        sb2 += __shfl_xor_sync(0xffffffffu, sb2, 1);
        sb2 += __shfl_xor_sync(0xffffffffu, sb2, 2);
        m_a = mna; m_b = mnb;
        l_a = l_a * aa + sa; l_b = l_b * ab + sb2;

#pragma unroll
        for (int n = 0; n < 16; n++) {
            o_[n][0] *= aa; o_[n][1] *= aa; o_[n][2] *= ab; o_[n][3] *= ab;
        }

#pragma unroll
        for (int kp = 0; kp < 4; kp++) {
            uint32_t ah4[4] = { pAh[2*kp], pBh[2*kp], pAh[2*kp+1], pBh[2*kp+1] };
            uint32_t al4[4] = { pAl[2*kp], pBl[2*kp], pAl[2*kp+1], pBl[2*kp+1] };
            int vrow = kp * 16 + (lane & 15);
#pragma unroll
            for (int nb = 0; nb < 8; nb++) {
                uint32_t ch = (uint32_t)(nb * 2 + lh);
                uint32_t voff = (uint32_t)(vrow * 256 + ((ch ^ (vrow & 15)) << 4));
                uint32_t h0, h1, h2, h3, l0, l1, l2, l3;
                LDSM4T(h0, h1, h2, h3, bs + 2 * ATT_PLANE_B + voff);
                LDSM4T(l0, l1, l2, l3, bs + 3 * ATT_PLANE_B + voff);
                uint32_t bh0[2] = { h0, h1 }, bh1[2] = { h2, h3 };
                uint32_t bl0[2] = { l0, l1 }, bl1[2] = { l2, l3 };
                MMA16816(o_[2*nb],   ah4, bh0); MMA16816(o_[2*nb],   ah4, bl0); MMA16816(o_[2*nb],   al4, bh0);
                MMA16816(o_[2*nb+1], ah4, bh1); MMA16816(o_[2*nb+1], ah4, bl1); MMA16816(o_[2*nb+1], al4, bh1);
            }
        }

        __syncthreads();
        if (kt + 2 < NKT) { load_kv(kt & 1, kt + 2); CP_COMMIT(); }
    }

    // ---- epilogue: split O/l into hi/lo planes directly ----
    float ia = 1.f / l_a, ib = 1.f / l_b;
    size_t r0 = (size_t)(b * SEQ + q0 + wrow + (lane >> 2)) * DMODEL + h * DHEAD + 2 * (lane & 3);
    size_t r1 = r0 + (size_t)8 * DMODEL;
#pragma unroll
    for (int n = 0; n < 16; n++) {
        __nv_bfloat16 hh, ll;
        split1(o_[n][0] * ia, hh, ll); ohi[r0 + n*8]     = hh; olo[r0 + n*8]     = ll;
        split1(o_[n][1] * ia, hh, ll); ohi[r0 + n*8 + 1] = hh; olo[r0 + n*8 + 1] = ll;
        split1(o_[n][2] * ib, hh, ll); ohi[r1 + n*8]     = hh; olo[r1 + n*8]     = ll;
        split1(o_[n][3] * ib, hh, ll); ohi[r1 + n*8 + 1] = hh; olo[r1 + n*8 + 1] = ll;
    }
}

// ============================================================================
extern "C" void kernel_launch(void* const* d_in, const int* in_sizes, int n_in,
                              void* d_out, int out_size)
{
    const float* x  = (const float*)d_in[0];
    const float* rc = (const float*)d_in[1];
    const float* rs = (const float*)d_in[2];
    const float* Wq = (const float*)d_in[3];
    const float* Wk = (const float*)d_in[4];
    const float* Wv = (const float*)d_in[5];
    const float* Wo = (const float*)d_in[6];
    float* out = (float*)d_out;

    float *q, *k, *v;
    cudaGetSymbolAddress((void**)&q, g_q);
    cudaGetSymbolAddress((void**)&k, g_k);
    cudaGetSymbolAddress((void**)&v, g_v);

    __nv_bfloat16 *xhi, *xlo, *wqhi, *wqlo, *wkhi, *wklo, *wvhi, *wvlo, *wohi, *wolo, *atthi, *attlo;
    __nv_bfloat16 *khi, *klo, *vhi, *vlo;
    cudaGetSymbolAddress((void**)&xhi,  g_xhi);   cudaGetSymbolAddress((void**)&xlo,  g_xlo);
    cudaGetSymbolAddress((void**)&wqhi, g_wqhi);  cudaGetSymbolAddress((void**)&wqlo, g_wqlo);
    cudaGetSymbolAddress((void**)&wkhi, g_wkhi);  cudaGetSymbolAddress((void**)&wklo, g_wklo);
    cudaGetSymbolAddress((void**)&wvhi, g_wvhi);  cudaGetSymbolAddress((void**)&wvlo, g_wvlo);
    cudaGetSymbolAddress((void**)&wohi, g_wohi);  cudaGetSymbolAddress((void**)&wolo, g_wolo);
    cudaGetSymbolAddress((void**)&atthi, g_atthi); cudaGetSymbolAddress((void**)&attlo, g_attlo);
    cudaGetSymbolAddress((void**)&khi, g_khi);    cudaGetSymbolAddress((void**)&klo, g_klo);
    cudaGetSymbolAddress((void**)&vhi, g_vhi);    cudaGetSymbolAddress((void**)&vlo, g_vlo);

    cudaFuncSetAttribute(gemm_fused, cudaFuncAttributeMaxDynamicSharedMemorySize, GEMM_SMEM);
    cudaFuncSetAttribute(attn_tc,    cudaFuncAttributeMaxDynamicSharedMemorySize, ATT_TC_SMEM);

    const int npx = MROWS * DMODEL / 2;
    const int npw = DMODEL * DMODEL / 2;
    pack_split<<<(npx + 255) / 256, 256>>>(x,  (uint32_t*)xhi,  (uint32_t*)xlo,  npx);
    pack_split<<<(npw + 255) / 256, 256>>>(Wq, (uint32_t*)wqhi, (uint32_t*)wqlo, npw);
    pack_split<<<(npw + 255) / 256, 256>>>(Wk, (uint32_t*)wkhi, (uint32_t*)wklo, npw);
    pack_split<<<(npw + 255) / 256, 256>>>(Wv, (uint32_t*)wvhi, (uint32_t*)wvlo, npw);
    pack_split<<<(npw + 255) / 256, 256>>>(Wo, (uint32_t*)wohi, (uint32_t*)wolo, npw);

    // fused QKV projection (z selects matrix)
    gemm_fused<<<dim3(DMODEL / 128, MROWS / 128, 3), 512, GEMM_SMEM>>>(
        xhi, xlo, wqhi, wqlo, wkhi, wklo, wvhi, wvlo, q, k, v);

    int rope_threads = BATCH * SEQ * NHEADS * 64;
    rope_pack<<<(rope_threads + 255) / 256, 256>>>(q, k, v, rc, rs, khi, klo, vhi, vlo);

    attn_tc<<<dim3(SEQ / 128, NHEADS, BATCH), 256, ATT_TC_SMEM>>>(q, khi, klo, vhi, vlo, atthi, attlo);

    // output projection
    gemm_fused<<<dim3(DMODEL / 128, MROWS / 128, 1), 512, GEMM_SMEM>>>(
        atthi, attlo, wohi, wolo, wohi, wolo, wohi, wolo, out, out, out);
}